// round 13
// baseline (speedup 1.0000x reference)
#include <cuda_runtime.h>
#include <cuda_bf16.h>

// VectorQuantizer on GB300 — bit-exact fp32 emulation, single fused launch.
// R13: R12 tiling (16 warps, k split 16-ways) with corrected z buffer sizing.
#define C_DIM   128
#define K_CODES 256
#define HW      4096
#define N_TOT   262144
#define BN      64
#define N_TILES (N_TOT / BN)     // 4096
#define NTH     512
#define NQ      33554432
#define GRID    148

// smem layout (floats)
#define E_OFF    0                        // embT [c][k] 32768
#define ZB_OFF   32768                    // 2 x 8192 raw z [buf][c][n]  (64n x 128c)
#define SE_OFF   (ZB_OFF + 16384)         // 256
#define AP_OFF   (SE_OFF + 256)           // 512 partials [part8][n64]
#define A_OFF    (AP_OFF + 512)           // 64
#define IDX_OFF  (A_OFF + 64)             // 64 ints
#define WS_OFF   (IDX_OFF + 64)           // 16
#define RED_OFF  (WS_OFF + 16)            // 2048 floats = 1024 ull keys [w16][n64]
#define SMEM_FLOATS (RED_OFF + 2048)
#define SMEM_BYTES  (SMEM_FLOATS * 4)     // 208448 B < 228 KB

__device__ double d_loss_arr[GRID];
__device__ int    d_done = 0;

// two independent IEEE-RN fma chains per instruction (lanes = adjacent k)
#define FMA2(d, a, b) asm("fma.rn.f32x2 %0, %1, %2, %0;" : "+l"(d) : "l"(a), "l"(b))

__device__ __forceinline__ unsigned long long dup2(float x) {
    unsigned long long r;
    unsigned u = __float_as_uint(x);
    asm("mov.b64 %0, {%1, %1};" : "=l"(r) : "r"(u));
    return r;
}

__device__ __forceinline__ void cp16(float* dst_smem, const float* src) {
    unsigned d = (unsigned)__cvta_generic_to_shared(dst_smem);
    asm volatile("cp.async.cg.shared.global [%0], [%1], 16;" :: "r"(d), "l"(src));
}
#define CP_COMMIT() asm volatile("cp.async.commit_group;")
#define CP_WAIT0()  asm volatile("cp.async.wait_group 0;")

// ---------------------------------------------------------------------------
__global__ void __launch_bounds__(NTH, 1)
vq_main(const float* __restrict__ z, const float* __restrict__ emb,
        float* __restrict__ out_q, float* __restrict__ out_idx,
        float* __restrict__ out_s) {
    extern __shared__ float smem[];
    float* e_s   = smem + E_OFF;
    float* zbuf0 = smem + ZB_OFF;
    float* zbuf1 = smem + ZB_OFF + 8192;
    float* se_s  = smem + SE_OFF;
    float* Ap    = smem + AP_OFF;
    float* A_s   = smem + A_OFF;
    int*   idx_s = (int*)(smem + IDX_OFF);
    float* wsum  = smem + WS_OFF;
    unsigned long long* red = (unsigned long long*)(smem + RED_OFF); // [16][64]

    const int tid  = threadIdx.x;
    const int lane = tid & 31, w = tid >> 5;     // 16 warps

    // ---- prologue: build embT [c][k] + se in smem directly from gmem ----
    if (tid < K_CODES) {
        int k = tid;
        const float4* er = (const float4*)(emb + (size_t)k * C_DIM);
        float s = 0.f;
        #pragma unroll 8
        for (int i = 0; i < 32; ++i) {
            float4 v = er[i];
            int c = i * 4;
            e_s[(c    ) * K_CODES + k] = v.x;
            e_s[(c + 1) * K_CODES + k] = v.y;
            e_s[(c + 2) * K_CODES + k] = v.z;
            e_s[(c + 3) * K_CODES + k] = v.w;
            s = __fmaf_rn(v.x, v.x, s); s = __fmaf_rn(v.y, v.y, s);
            s = __fmaf_rn(v.z, v.z, s); s = __fmaf_rn(v.w, v.w, s);
        }
        se_s[k] = s;   // sequential fused-fma chain, c ascending (R3 numerics)
    }

    // tiling: warp w owns codes [16w, 16w+16); kq = half-warp k-sel, nq = n quad
    const int kq = lane & 1, nq = lane >> 1;      // nq: 0..15
    const int n0 = nq * 4;
    const int k0 = w * 16 + kq * 8;
    float lsum_tot = 0.f;

    // ---- prefetch first z tile ----
    int tile = blockIdx.x;
    {
        int b = tile >> 6, hw0 = (tile & 63) << 6;
        const float* zb = z + (size_t)b * (C_DIM * HW) + hw0;
        #pragma unroll
        for (int i = 0; i < 4; ++i) {
            int idx = tid + i * NTH;              // 2048 float4
            int c = idx >> 4, n4 = (idx & 15) << 2;
            cp16(zbuf0 + c * 64 + n4, zb + (size_t)c * HW + n4);
        }
        CP_COMMIT();
    }

    int buf = 0;
    for (; tile < N_TILES; tile += GRID) {
        float* zcur = buf ? zbuf1 : zbuf0;
        float* znxt = buf ? zbuf0 : zbuf1;

        CP_WAIT0();
        __syncthreads();

        int next = tile + GRID;
        if (next < N_TILES) {
            int b = next >> 6, hw0 = (next & 63) << 6;
            const float* zb = z + (size_t)b * (C_DIM * HW) + hw0;
            #pragma unroll
            for (int i = 0; i < 4; ++i) {
                int idx = tid + i * NTH;
                int c = idx >> 4, n4 = (idx & 15) << 2;
                cp16(znxt + c * 64 + n4, zb + (size_t)c * HW + n4);
            }
            CP_COMMIT();
        }

        // ---- A_n via 8 partial fused-fma chains (argmin-invariant order) ----
        {
            int n = tid & 63, part = tid >> 6;    // 8 parts of 16 c
            const float* zp = zcur + part * 16 * 64 + n;
            float a = 0.f;
            #pragma unroll 8
            for (int c = 0; c < 16; ++c) { float v = zp[c * 64]; a = fmaf(v, v, a); }
            Ap[part * 64 + n] = a;
        }
        __syncthreads();
        if (tid < 64) {
            float a = Ap[tid];
            #pragma unroll
            for (int p = 1; p < 8; ++p) a = a + Ap[p * 64 + tid];
            A_s[tid] = a;
        }
        __syncthreads();

        // ---- mainloop: G[n,k] sequential fused-fma over c = 0..127 ----
        unsigned long long acc[4][4];
        #pragma unroll
        for (int i = 0; i < 4; ++i)
            #pragma unroll
            for (int j = 0; j < 4; ++j) acc[i][j] = 0ULL;

        #pragma unroll 4
        for (int c = 0; c < C_DIM; ++c) {
            float4 q0 = *(const float4*)(zcur + c * 64 + n0);       // bcast pairs
            const ulonglong2* ep = (const ulonglong2*)(e_s + c * K_CODES + k0);
            ulonglong2 e0 = ep[0], e1 = ep[1];                      // half-warp bcast
            unsigned long long A4[4] = {dup2(q0.x), dup2(q0.y), dup2(q0.z), dup2(q0.w)};
            unsigned long long B4[4] = {e0.x, e0.y, e1.x, e1.y};
            #pragma unroll
            for (int j = 0; j < 4; ++j)
                #pragma unroll
                for (int i = 0; i < 4; ++i) FMA2(acc[i][j], A4[i], B4[j]);
        }

        // ---- argmin: d = RN(RN(A - 2G) + se_k); kq-reduce then cross-warp ----
        #pragma unroll
        for (int i = 0; i < 4; ++i) {
            float An = A_s[n0 + i];
            unsigned long long best = 0ULL;
            #pragma unroll
            for (int j = 0; j < 4; ++j) {
                float2 g = *(float2*)&acc[i][j];
                int ka = k0 + 2 * j, kb = ka + 1;
                float da = __fadd_rn(__fadd_rn(An, -__fmul_rn(2.0f, g.x)), se_s[ka]);
                float db = __fadd_rn(__fadd_rn(An, -__fmul_rn(2.0f, g.y)), se_s[kb]);
                unsigned va = __float_as_uint(da);
                va = ((int)va < 0) ? ~va : (va | 0x80000000u);
                unsigned vb = __float_as_uint(db);
                vb = ((int)vb < 0) ? ~vb : (vb | 0x80000000u);
                unsigned long long keya = ((unsigned long long)(~va) << 32) | (unsigned)(255 - ka);
                unsigned long long keyb = ((unsigned long long)(~vb) << 32) | (unsigned)(255 - kb);
                if (keya > best) best = keya;
                if (keyb > best) best = keyb;
            }
            {   // combine kq=0/1 halves
                unsigned long long o = __shfl_xor_sync(0xFFFFFFFFu, best, 1);
                if (o > best) best = o;
            }
            if (kq == 0) red[w * 64 + n0 + i] = best;
        }
        __syncthreads();
        if (tid < 64) {   // combine the 16 warps' 16-k slices
            unsigned long long best = red[tid];
            #pragma unroll
            for (int ww = 1; ww < 16; ++ww) {
                unsigned long long o = red[ww * 64 + tid];
                if (o > best) best = o;
            }
            idx_s[tid] = 255 - (int)(best & 0xFFFFFFFFull);
        }
        __syncthreads();

        // ---- epilogue: q_ste = RN(z + RN(q-z)); loss += RN(q-z)^2 ----
        {
            int b = tile >> 6, hw0 = (tile & 63) << 6;
            float* outb = out_q + (size_t)b * (C_DIM * HW) + hw0;
            #pragma unroll
            for (int i = 0; i < 4; ++i) {
                int idx = tid + i * NTH;           // 2048 float4
                int c = idx >> 4, n4 = (idx & 15) << 2;
                float4 zv = *(const float4*)(zcur + c * 64 + n4);
                int ka = idx_s[n4], kb = idx_s[n4 + 1], kc = idx_s[n4 + 2], kd = idx_s[n4 + 3];
                const float* ec = e_s + c * K_CODES;
                float d0 = ec[ka] - zv.x, d1 = ec[kb] - zv.y;
                float d2 = ec[kc] - zv.z, d3 = ec[kd] - zv.w;
                lsum_tot = fmaf(d0, d0, lsum_tot);
                lsum_tot = fmaf(d1, d1, lsum_tot);
                lsum_tot = fmaf(d2, d2, lsum_tot);
                lsum_tot = fmaf(d3, d3, lsum_tot);
                float4 o = make_float4(zv.x + d0, zv.y + d1, zv.z + d2, zv.w + d3);
                *(float4*)(outb + (size_t)c * HW + n4) = o;
            }
            if (out_idx != nullptr && tid < 64)
                out_idx[(size_t)tile * BN + tid] = (float)idx_s[tid];
        }
        buf ^= 1;
    }

    // ---- per-CTA loss slot + last-block in-kernel finalize ----
    #pragma unroll
    for (int off = 16; off > 0; off >>= 1)
        lsum_tot += __shfl_xor_sync(0xFFFFFFFFu, lsum_tot, off);
    if (lane == 0) wsum[w] = lsum_tot;
    __syncthreads();
    if (tid == 0) {
        float t = 0.f;
        #pragma unroll
        for (int ww = 0; ww < 16; ++ww) t += wsum[ww];
        d_loss_arr[blockIdx.x] = (double)t;
        __threadfence();
        int old = atomicAdd(&d_done, 1);
        if (old == GRID - 1) {                 // last block: deterministic sum
            __threadfence();
            double s = 0.0;
            volatile double* la = d_loss_arr;
            for (int i = 0; i < GRID; ++i) s += la[i];
            double mse = s * (1.0 / (double)NQ);
            if (out_s != nullptr) {
                out_s[0] = (float)(0.25 * mse);
                out_s[1] = (float)mse;
            }
            d_done = 0;                        // reset for next graph replay
            __threadfence();
        }
    }
}

extern "C" void kernel_launch(void* const* d_in, const int* in_sizes, int n_in,
                              void* d_out, int out_size) {
    const float *z, *emb;
    if (n_in >= 2 && in_sizes[0] == K_CODES * C_DIM) {
        emb = (const float*)d_in[0];
        z   = (const float*)d_in[1];
    } else {
        z   = (const float*)d_in[0];
        emb = (const float*)d_in[1];
    }
    float* out = (float*)d_out;

    cudaFuncSetAttribute(vq_main, cudaFuncAttributeMaxDynamicSharedMemorySize,
                         SMEM_BYTES);

    float* out_idx = nullptr;
    float* out_s   = nullptr;
    long long osz = (long long)out_size;
    if (osz >= (long long)NQ + N_TOT)     out_idx = out + NQ;
    if (osz >= (long long)NQ + N_TOT + 2) out_s   = out + NQ + N_TOT;

    vq_main<<<GRID, NTH, SMEM_BYTES>>>(z, emb, out, out_idx, out_s);
}